// round 2
// baseline (speedup 1.0000x reference)
#include <cuda_runtime.h>
#include <math.h>

#define NX    2000
#define NZ    4
#define TT    16
#define KDIM  24000   // 3*2000*4
#define NOUT  8000    // nz*nx
#define NCOL  64      // TT*NZ

__device__ float g_zctx[TT * KDIM];   // (16, 24000)
__device__ float g_zg[NX * NCOL];     // (2000, 64), col n = t*4+z

union F2U { float2 f; unsigned long long u; };
__device__ __forceinline__ void ffma2(F2U& d, const F2U a, const F2U b) {
    asm("fma.rn.f32x2 %0, %1, %2, %0;" : "+l"(d.u) : "l"(a.u), "l"(b.u));
}

// ---------- kernel 1: gather ----------
__global__ void gather_kernel(const float* __restrict__ factors,
                              const int*   __restrict__ t_idx) {
    int gid = blockIdx.x * blockDim.x + threadIdx.x;
    if (gid < NX * NCOL) {
        int y = gid >> 6, n = gid & 63;
        int t = n >> 2, zi = n & 3;
        g_zg[gid] = factors[(long)t_idx[t] * NOUT + y * NZ + zi];
    } else {
        int i = gid - NX * NCOL;            // identity block copy, float4
        if (i < TT * NOUT / 4) {
            int t = i / (NOUT / 4);
            int j = i - t * (NOUT / 4);
            float4 v = ((const float4*)factors)[(long)t_idx[t] * (NOUT / 4) + j];
            ((float4*)g_zctx)[(long)t * (KDIM / 4) + j] = v;
        }
    }
}

// ---------- kernel 2: relation GEMM (4000x2000)@(2000x64) ----------
#define KT1 100
__global__ __launch_bounds__(128) void gemm1_kernel(const float* __restrict__ rel) {
    __shared__ float rel_sT[KT1][36];  // [k][m] padded
    __shared__ float zg_s[KT1][64];    // [k][n]
    int tid = threadIdx.x;
    int mg = tid >> 4;     // 0..7 -> 4 m rows
    int ng = tid & 15;     // 0..15 -> 4 n cols
    int mbase = blockIdx.x * 32;

    F2U acc[2][4];
    #pragma unroll
    for (int a = 0; a < 2; a++)
        #pragma unroll
        for (int b = 0; b < 4; b++) acc[a][b].f = make_float2(0.f, 0.f);

    for (int kt = 0; kt < NX; kt += KT1) {
        for (int i = tid; i < 32 * (KT1 / 4); i += 128) {
            int m = i / (KT1 / 4), q = i - m * (KT1 / 4);
            float4 v = *(const float4*)&rel[(long)(mbase + m) * NX + kt + q * 4];
            rel_sT[q*4+0][m] = v.x; rel_sT[q*4+1][m] = v.y;
            rel_sT[q*4+2][m] = v.z; rel_sT[q*4+3][m] = v.w;
        }
        for (int i = tid; i < KT1 * 64 / 4; i += 128)
            ((float4*)zg_s)[i] = ((const float4*)(g_zg + kt * 64))[i];
        __syncthreads();

        #pragma unroll 4
        for (int k = 0; k < KT1; k++) {
            float4 a4 = *(float4*)&rel_sT[k][mg * 4];
            float4 b4 = *(float4*)&zg_s[k][ng * 4];
            F2U a2[2];
            a2[0].f = make_float2(a4.x, a4.y);
            a2[1].f = make_float2(a4.z, a4.w);
            float bb[4] = {b4.x, b4.y, b4.z, b4.w};
            #pragma unroll
            for (int j = 0; j < 4; j++) {
                F2U b2; b2.f = make_float2(bb[j], bb[j]);
                ffma2(acc[0][j], a2[0], b2);
                ffma2(acc[1][j], a2[1], b2);
            }
        }
        __syncthreads();
    }
    // scatter: m = 2x + (r-1); col n=(ng*4+j) -> t=ng, z=j
    #pragma unroll
    for (int mp = 0; mp < 2; mp++)
        #pragma unroll
        for (int j = 0; j < 4; j++) {
            int m0 = mbase + mg * 4 + mp * 2;   // even
            float2 v = acc[mp][j].f;
            g_zctx[(long)ng * KDIM + 1 * NOUT + (m0 >> 1) * NZ + j] = v.x;
            g_zctx[(long)ng * KDIM + 2 * NOUT + (m0 >> 1) * NZ + j] = v.y;
        }
}

// ---------- kernel 3: MLP out = tanh(zctx @ W^T + b) ----------
#define KTILE 1920
#define ROWS  8
#define WARPS 7
__global__ __launch_bounds__(224) void mlp_kernel(const float* __restrict__ W,
                                                  const float* __restrict__ bias,
                                                  float* __restrict__ out) {
    extern __shared__ float zs[];       // [16][KTILE]
    int tid = threadIdx.x, warp = tid >> 5, lane = tid & 31;
    int row0 = blockIdx.x * (WARPS * ROWS) + warp * ROWS;
    if (row0 > NOUT - ROWS) row0 = NOUT - ROWS;   // benign duplicates
    const float* wb = W + (long)row0 * KDIM;

    F2U acc[ROWS][8];
    #pragma unroll
    for (int r = 0; r < ROWS; r++)
        #pragma unroll
        for (int tp = 0; tp < 8; tp++) acc[r][tp].f = make_float2(0.f, 0.f);

    for (int kt = 0; kt < KDIM; kt += KTILE) {
        int tl = (KDIM - kt < KTILE) ? (KDIM - kt) : KTILE;
        int nf4 = (TT * tl) >> 2;
        for (int i = tid; i < nf4; i += WARPS * 32) {
            int e = i << 2;
            int t = e / tl;
            int kk = e - t * tl;
            *(float4*)&zs[t * KTILE + kk] =
                *(const float4*)&g_zctx[(long)t * KDIM + kt + kk];
        }
        __syncthreads();

        for (int kk = 0; kk < tl; kk += 128) {
            int kl = kk + lane * 4;
            if (kl < tl) {
                F2U z2[8][4];
                #pragma unroll
                for (int tp = 0; tp < 8; tp++) {
                    float4 za = *(float4*)&zs[(2*tp)   * KTILE + kl];
                    float4 zb = *(float4*)&zs[(2*tp+1) * KTILE + kl];
                    z2[tp][0].f = make_float2(za.x, zb.x);
                    z2[tp][1].f = make_float2(za.y, zb.y);
                    z2[tp][2].f = make_float2(za.z, zb.z);
                    z2[tp][3].f = make_float2(za.w, zb.w);
                }
                const float* wk = wb + kt + kl;
                #pragma unroll
                for (int rg = 0; rg < 2; rg++) {
                    float4 wv[4];
                    #pragma unroll
                    for (int r = 0; r < 4; r++)
                        wv[r] = *(const float4*)&wk[(long)(rg * 4 + r) * KDIM];
                    #pragma unroll
                    for (int r = 0; r < 4; r++) {
                        float ws[4] = {wv[r].x, wv[r].y, wv[r].z, wv[r].w};
                        #pragma unroll
                        for (int i = 0; i < 4; i++) {
                            F2U w2; w2.f = make_float2(ws[i], ws[i]);
                            #pragma unroll
                            for (int tp = 0; tp < 8; tp++)
                                ffma2(acc[rg * 4 + r][tp], w2, z2[tp][i]);
                        }
                    }
                }
            }
        }
        __syncthreads();
    }

    #pragma unroll
    for (int r = 0; r < ROWS; r++) {
        int n = row0 + r;
        #pragma unroll
        for (int tp = 0; tp < 8; tp++) {
            float2 v = acc[r][tp].f;
            #pragma unroll
            for (int off = 16; off > 0; off >>= 1) {
                v.x += __shfl_down_sync(0xffffffffu, v.x, off);
                v.y += __shfl_down_sync(0xffffffffu, v.y, off);
            }
            if (lane == 0) {
                float bb = bias[n];
                out[(long)(2*tp)   * NOUT + n] = tanhf(v.x + bb);
                out[(long)(2*tp+1) * NOUT + n] = tanhf(v.y + bb);
            }
        }
    }
}

extern "C" void kernel_launch(void* const* d_in, const int* in_sizes, int n_in,
                              void* d_out, int out_size) {
    const float* relations = (const float*)d_in[0];
    const float* factors   = (const float*)d_in[1];
    const float* W_dyn     = (const float*)d_in[2];
    const float* b_dyn     = (const float*)d_in[3];
    const int*   t_idx     = (const int*)d_in[4];
    float* out = (float*)d_out;

    cudaFuncSetAttribute(mlp_kernel, cudaFuncAttributeMaxDynamicSharedMemorySize,
                         TT * KTILE * (int)sizeof(float));

    gather_kernel<<<625, 256>>>(factors, t_idx);
    gemm1_kernel<<<125, 128>>>(relations);
    int mlp_blocks = (NOUT + WARPS * ROWS - 1) / (WARPS * ROWS);  // 143
    mlp_kernel<<<mlp_blocks, WARPS * 32, TT * KTILE * sizeof(float)>>>(W_dyn, b_dyn, out);
}

// round 3
// speedup vs baseline: 1.2211x; 1.2211x over previous
#include <cuda_runtime.h>
#include <math.h>

#define NX    2000
#define NZ    4
#define TT    16
#define KDIM  24000   // 3*2000*4
#define NOUT  8000    // nz*nx
#define NCOL  64      // TT*NZ

__device__ float g_zctx[TT * KDIM];   // (16, 24000)
__device__ float g_zg[NX * NCOL];     // (2000, 64), col n = t*4+z

union F2U { float2 f; unsigned long long u; };
__device__ __forceinline__ void ffma2(F2U& d, const F2U a, const F2U b) {
    asm("fma.rn.f32x2 %0, %1, %2, %0;" : "+l"(d.u) : "l"(a.u), "l"(b.u));
}

// ---------- kernel 1: gather ----------
__global__ void gather_kernel(const float* __restrict__ factors,
                              const int*   __restrict__ t_idx) {
    int gid = blockIdx.x * blockDim.x + threadIdx.x;
    if (gid < NX * NCOL) {
        int y = gid >> 6, n = gid & 63;
        int t = n >> 2, zi = n & 3;
        g_zg[gid] = factors[(long)t_idx[t] * NOUT + y * NZ + zi];
    } else {
        int i = gid - NX * NCOL;            // identity block copy, float4
        if (i < TT * NOUT / 4) {
            int t = i / (NOUT / 4);
            int j = i - t * (NOUT / 4);
            float4 v = ((const float4*)factors)[(long)t_idx[t] * (NOUT / 4) + j];
            ((float4*)g_zctx)[(long)t * (KDIM / 4) + j] = v;
        }
    }
}

// ---------- kernel 2: relation GEMM (4000x2000)@(2000x64) ----------
#define KT1 100
__global__ __launch_bounds__(128) void gemm1_kernel(const float* __restrict__ rel) {
    __shared__ float rel_sT[KT1][36];  // [k][m] padded
    __shared__ float zg_s[KT1][64];    // [k][n]
    int tid = threadIdx.x;
    int mg = tid >> 4;     // 0..7 -> 4 m rows
    int ng = tid & 15;     // 0..15 -> 4 n cols
    int mbase = blockIdx.x * 32;

    F2U acc[2][4];
    #pragma unroll
    for (int a = 0; a < 2; a++)
        #pragma unroll
        for (int b = 0; b < 4; b++) acc[a][b].f = make_float2(0.f, 0.f);

    for (int kt = 0; kt < NX; kt += KT1) {
        for (int i = tid; i < 32 * (KT1 / 4); i += 128) {
            int m = i / (KT1 / 4), q = i - m * (KT1 / 4);
            float4 v = *(const float4*)&rel[(long)(mbase + m) * NX + kt + q * 4];
            rel_sT[q*4+0][m] = v.x; rel_sT[q*4+1][m] = v.y;
            rel_sT[q*4+2][m] = v.z; rel_sT[q*4+3][m] = v.w;
        }
        for (int i = tid; i < KT1 * 64 / 4; i += 128)
            ((float4*)zg_s)[i] = ((const float4*)(g_zg + kt * 64))[i];
        __syncthreads();

        #pragma unroll 4
        for (int k = 0; k < KT1; k++) {
            float4 a4 = *(float4*)&rel_sT[k][mg * 4];
            float4 b4 = *(float4*)&zg_s[k][ng * 4];
            F2U a2[2];
            a2[0].f = make_float2(a4.x, a4.y);
            a2[1].f = make_float2(a4.z, a4.w);
            float bb[4] = {b4.x, b4.y, b4.z, b4.w};
            #pragma unroll
            for (int j = 0; j < 4; j++) {
                F2U b2; b2.f = make_float2(bb[j], bb[j]);
                ffma2(acc[0][j], a2[0], b2);
                ffma2(acc[1][j], a2[1], b2);
            }
        }
        __syncthreads();
    }
    // scatter: m = 2x + (r-1); col n=(ng*4+j) -> t=ng, z=j
    #pragma unroll
    for (int mp = 0; mp < 2; mp++)
        #pragma unroll
        for (int j = 0; j < 4; j++) {
            int m0 = mbase + mg * 4 + mp * 2;   // even
            float2 v = acc[mp][j].f;
            g_zctx[(long)ng * KDIM + 1 * NOUT + (m0 >> 1) * NZ + j] = v.x;
            g_zctx[(long)ng * KDIM + 2 * NOUT + (m0 >> 1) * NZ + j] = v.y;
        }
}

// ---------- kernel 3: MLP out = tanh(zctx @ W^T + b) ----------
// 14 warps: 7 row-groups x 2 t-halves. Warp owns 8 W rows x 8 t.
// Per-lane: acc[8][4] F2U = 64 regs, z2[4][4] F2U = 32 regs -> no spills.
#define KTILE 1920
#define ROWS  8
#define NWARP 14
__global__ __launch_bounds__(NWARP * 32) void mlp_kernel(const float* __restrict__ W,
                                                         const float* __restrict__ bias,
                                                         float* __restrict__ out) {
    extern __shared__ float zs[];       // [16][KTILE]
    int tid = threadIdx.x, warp = tid >> 5, lane = tid & 31;
    int rowgrp = warp % 7;
    int tbase  = (warp / 7) * 8;        // 0 or 8
    int row0 = blockIdx.x * 56 + rowgrp * ROWS;
    if (row0 > NOUT - ROWS) row0 = NOUT - ROWS;   // benign duplicates
    const float* wb = W + (long)row0 * KDIM;

    F2U acc[ROWS][4];
    #pragma unroll
    for (int r = 0; r < ROWS; r++)
        #pragma unroll
        for (int tp = 0; tp < 4; tp++) acc[r][tp].f = make_float2(0.f, 0.f);

    for (int kt = 0; kt < KDIM; kt += KTILE) {
        int tl = (KDIM - kt < KTILE) ? (KDIM - kt) : KTILE;
        int nf4 = (TT * tl) >> 2;
        for (int i = tid; i < nf4; i += NWARP * 32) {
            int e = i << 2;
            int t = e / tl;
            int kk = e - t * tl;
            *(float4*)&zs[t * KTILE + kk] =
                *(const float4*)&g_zctx[(long)t * KDIM + kt + kk];
        }
        __syncthreads();

        for (int kk = 0; kk < tl; kk += 128) {
            int kl = kk + lane * 4;
            if (kl < tl) {
                // z fragment: 4 k x 8 t (this warp's t-half), packed t-pairs
                F2U z2[4][4];
                #pragma unroll
                for (int tp = 0; tp < 4; tp++) {
                    float4 za = *(float4*)&zs[(tbase + 2*tp)     * KTILE + kl];
                    float4 zb = *(float4*)&zs[(tbase + 2*tp + 1) * KTILE + kl];
                    z2[tp][0].f = make_float2(za.x, zb.x);
                    z2[tp][1].f = make_float2(za.y, zb.y);
                    z2[tp][2].f = make_float2(za.z, zb.z);
                    z2[tp][3].f = make_float2(za.w, zb.w);
                }
                const float* wk = wb + kt + kl;
                #pragma unroll
                for (int rg = 0; rg < 2; rg++) {
                    float4 wv[4];
                    #pragma unroll
                    for (int r = 0; r < 4; r++)
                        wv[r] = *(const float4*)&wk[(long)(rg * 4 + r) * KDIM];
                    #pragma unroll
                    for (int r = 0; r < 4; r++) {
                        float ws[4] = {wv[r].x, wv[r].y, wv[r].z, wv[r].w};
                        #pragma unroll
                        for (int i = 0; i < 4; i++) {
                            F2U w2; w2.f = make_float2(ws[i], ws[i]);
                            #pragma unroll
                            for (int tp = 0; tp < 4; tp++)
                                ffma2(acc[rg * 4 + r][tp], w2, z2[tp][i]);
                        }
                    }
                }
            }
        }
        __syncthreads();
    }

    #pragma unroll
    for (int r = 0; r < ROWS; r++) {
        int n = row0 + r;
        #pragma unroll
        for (int tp = 0; tp < 4; tp++) {
            float2 v = acc[r][tp].f;
            #pragma unroll
            for (int off = 16; off > 0; off >>= 1) {
                v.x += __shfl_down_sync(0xffffffffu, v.x, off);
                v.y += __shfl_down_sync(0xffffffffu, v.y, off);
            }
            if (lane == 0) {
                float bb = bias[n];
                out[(long)(tbase + 2*tp)     * NOUT + n] = tanhf(v.x + bb);
                out[(long)(tbase + 2*tp + 1) * NOUT + n] = tanhf(v.y + bb);
            }
        }
    }
}

extern "C" void kernel_launch(void* const* d_in, const int* in_sizes, int n_in,
                              void* d_out, int out_size) {
    const float* relations = (const float*)d_in[0];
    const float* factors   = (const float*)d_in[1];
    const float* W_dyn     = (const float*)d_in[2];
    const float* b_dyn     = (const float*)d_in[3];
    const int*   t_idx     = (const int*)d_in[4];
    float* out = (float*)d_out;

    cudaFuncSetAttribute(mlp_kernel, cudaFuncAttributeMaxDynamicSharedMemorySize,
                         TT * KTILE * (int)sizeof(float));

    gather_kernel<<<625, 256>>>(factors, t_idx);
    gemm1_kernel<<<125, 128>>>(relations);
    int mlp_blocks = (NOUT + 55) / 56;   // 143
    mlp_kernel<<<mlp_blocks, NWARP * 32, TT * KTILE * sizeof(float)>>>(W_dyn, b_dyn, out);
}

// round 5
// speedup vs baseline: 1.5910x; 1.3030x over previous
#include <cuda_runtime.h>
#include <math.h>
#include <stdint.h>

#define NX    2000
#define NZ    4
#define TT    16
#define KDIM  24000   // 3*2000*4
#define NOUT  8000    // nz*nx
#define NCOL  64      // TT*NZ

#define KSPLIT 9
#define NTILES 375    // 24000/64
#define TPK    42     // ceil(375/9)
#define KT     64

__device__ float  g_zctx[TT * KDIM];          // (16, 24000)
__device__ float  g_zg[NX * NCOL];            // (2000, 64)
__device__ float2 g_zpair[8 * KDIM];          // [tp][k] = (z[2tp][k], z[2tp+1][k])
__device__ float  g_scratch[KSPLIT * NOUT * TT];  // [kb][n][t]

union F2U { float2 f; unsigned long long u; };
__device__ __forceinline__ void ffma2(F2U& d, const F2U a, const F2U b) {
    asm("fma.rn.f32x2 %0, %1, %2, %0;" : "+l"(d.u) : "l"(a.u), "l"(b.u));
}
__device__ __forceinline__ uint32_t s2u(const void* p) {
    uint32_t a;
    asm("{ .reg .u64 t; cvta.to.shared.u64 t, %1; cvt.u32.u64 %0, t; }" : "=r"(a) : "l"(p));
    return a;
}
#define CP16(dst, src) asm volatile("cp.async.cg.shared.global [%0], [%1], 16;" :: "r"(dst), "l"(src))
#define CP_COMMIT()    asm volatile("cp.async.commit_group;")
#define CP_WAIT(N)     asm volatile("cp.async.wait_group %0;" :: "n"(N))

// ---------- kernel 1: gather ----------
__global__ void gather_kernel(const float* __restrict__ factors,
                              const int*   __restrict__ t_idx) {
    int gid = blockIdx.x * blockDim.x + threadIdx.x;
    if (gid < NX * NCOL) {
        int y = gid >> 6, n = gid & 63;
        int t = n >> 2, zi = n & 3;
        g_zg[gid] = factors[(long)t_idx[t] * NOUT + y * NZ + zi];
    } else {
        int i = gid - NX * NCOL;
        if (i < TT * NOUT / 4) {
            int t = i / (NOUT / 4);
            int j = i - t * (NOUT / 4);
            float4 v = ((const float4*)factors)[(long)t_idx[t] * (NOUT / 4) + j];
            ((float4*)g_zctx)[(long)t * (KDIM / 4) + j] = v;
        }
    }
}

// ---------- kernel 2: relation GEMM (4000x2000)@(2000x64) ----------
#define KT1 100
__global__ __launch_bounds__(128) void gemm1_kernel(const float* __restrict__ rel) {
    __shared__ float rel_sT[KT1][36];
    __shared__ float zg_s[KT1][64];
    int tid = threadIdx.x;
    int mg = tid >> 4, ng = tid & 15;
    int mbase = blockIdx.x * 32;

    F2U acc[2][4];
    #pragma unroll
    for (int a = 0; a < 2; a++)
        #pragma unroll
        for (int b = 0; b < 4; b++) acc[a][b].f = make_float2(0.f, 0.f);

    for (int kt = 0; kt < NX; kt += KT1) {
        for (int i = tid; i < 32 * (KT1 / 4); i += 128) {
            int m = i / (KT1 / 4), q = i - m * (KT1 / 4);
            float4 v = *(const float4*)&rel[(long)(mbase + m) * NX + kt + q * 4];
            rel_sT[q*4+0][m] = v.x; rel_sT[q*4+1][m] = v.y;
            rel_sT[q*4+2][m] = v.z; rel_sT[q*4+3][m] = v.w;
        }
        for (int i = tid; i < KT1 * 64 / 4; i += 128)
            ((float4*)zg_s)[i] = ((const float4*)(g_zg + kt * 64))[i];
        __syncthreads();

        #pragma unroll 4
        for (int k = 0; k < KT1; k++) {
            float4 a4 = *(float4*)&rel_sT[k][mg * 4];
            float4 b4 = *(float4*)&zg_s[k][ng * 4];
            F2U a2[2];
            a2[0].f = make_float2(a4.x, a4.y);
            a2[1].f = make_float2(a4.z, a4.w);
            float bb[4] = {b4.x, b4.y, b4.z, b4.w};
            #pragma unroll
            for (int j = 0; j < 4; j++) {
                F2U b2; b2.f = make_float2(bb[j], bb[j]);
                ffma2(acc[0][j], a2[0], b2);
                ffma2(acc[1][j], a2[1], b2);
            }
        }
        __syncthreads();
    }
    #pragma unroll
    for (int mp = 0; mp < 2; mp++)
        #pragma unroll
        for (int j = 0; j < 4; j++) {
            int m0 = mbase + mg * 4 + mp * 2;
            float2 v = acc[mp][j].f;
            g_zctx[(long)ng * KDIM + 1 * NOUT + (m0 >> 1) * NZ + j] = v.x;
            g_zctx[(long)ng * KDIM + 2 * NOUT + (m0 >> 1) * NZ + j] = v.y;
        }
}

// ---------- kernel 2.5: pack z into t-pairs ----------
__global__ void pack_kernel() {
    int gid = blockIdx.x * blockDim.x + threadIdx.x;
    if (gid < 8 * KDIM) {
        int tp = gid / KDIM, k = gid - tp * KDIM;
        g_zpair[gid] = make_float2(g_zctx[(2*tp) * KDIM + k],
                                   g_zctx[(2*tp + 1) * KDIM + k]);
    }
}

// ---------- kernel 3: MLP partial GEMM, double-buffered cp.async ----------
// smem: W [2][128][68] floats (69632 B) + Z [2][8][132] floats (8448 B) = 78080 B
#define WSTRIDE 68
#define ZSTRIDE 132           // floats per tp row (66 float2)
#define WBUF    (128 * WSTRIDE)
#define ZBASE   (2 * WBUF)
#define ZBUF    (8 * ZSTRIDE)

__global__ __launch_bounds__(256) void mlp_kernel(const float* __restrict__ W) {
    extern __shared__ float sm[];
    int tid  = threadIdx.x;
    int lane = tid & 31, warp = tid >> 5;
    int rowblk = blockIdx.x, kb = blockIdx.y;

    int row0 = rowblk * 128;
    if (row0 > NOUT - 128) row0 = NOUT - 128;     // benign duplicate rows
    int t0 = kb * TPK;
    int t1 = t0 + TPK; if (t1 > NTILES) t1 = NTILES;
    int nt = t1 - t0;

    // thread tile: rows (ra, ra+64) x t-pairs (tp0, tp0+1)
    int rg  = lane >> 2;            // 0..7
    int tpg = lane & 3;             // 0..3
    int ra  = warp * 8 + rg;        // 0..63
    int rb  = ra + 64;
    int tp0 = tpg * 2;

    F2U acc00, acc01, acc10, acc11;
    acc00.f = acc01.f = acc10.f = acc11.f = make_float2(0.f, 0.f);

    auto load_tile = [&](int tile, int buf) {
        int k0 = (t0 + tile) * KT;
        // W: 128 rows x 64 floats = 2048 CP16s of 4 floats
        #pragma unroll
        for (int j = 0; j < 8; j++) {
            int c = j * 256 + tid;
            int row = c >> 4, q = c & 15;
            uint32_t dst = s2u(&sm[buf * WBUF + row * WSTRIDE + q * 4]);
            const float* src = &W[(size_t)(row0 + row) * KDIM + k0 + q * 4];
            CP16(dst, src);
        }
        // Z: 8 tp-rows x 64 float2 = 256 CP16s
        {
            int tp = tid >> 5, ch = tid & 31;
            uint32_t dst = s2u(&sm[ZBASE + buf * ZBUF + tp * ZSTRIDE + ch * 4]);
            const float2* src = &g_zpair[tp * KDIM + k0 + ch * 2];
            CP16(dst, src);
        }
        CP_COMMIT();
    };

    load_tile(0, 0);
    for (int i = 0; i < nt; i++) {
        int buf = i & 1;
        if (i + 1 < nt) { load_tile(i + 1, buf ^ 1); CP_WAIT(1); }
        else           { CP_WAIT(0); }
        __syncthreads();

        const float* Wt = &sm[buf * WBUF];
        const float* Zt = &sm[ZBASE + buf * ZBUF];
        #pragma unroll 4
        for (int kk = 0; kk < KT; kk += 4) {
            float4 wa = *(const float4*)&Wt[ra * WSTRIDE + kk];
            float4 wb = *(const float4*)&Wt[rb * WSTRIDE + kk];
            float4 z0a = *(const float4*)&Zt[tp0 * ZSTRIDE + kk * 2];
            float4 z0b = *(const float4*)&Zt[tp0 * ZSTRIDE + kk * 2 + 4];
            float4 z1a = *(const float4*)&Zt[(tp0 + 1) * ZSTRIDE + kk * 2];
            float4 z1b = *(const float4*)&Zt[(tp0 + 1) * ZSTRIDE + kk * 2 + 4];
            F2U za[4], zb[4];
            za[0].f = make_float2(z0a.x, z0a.y); za[1].f = make_float2(z0a.z, z0a.w);
            za[2].f = make_float2(z0b.x, z0b.y); za[3].f = make_float2(z0b.z, z0b.w);
            zb[0].f = make_float2(z1a.x, z1a.y); zb[1].f = make_float2(z1a.z, z1a.w);
            zb[2].f = make_float2(z1b.x, z1b.y); zb[3].f = make_float2(z1b.z, z1b.w);
            float was[4] = {wa.x, wa.y, wa.z, wa.w};
            float wbs[4] = {wb.x, wb.y, wb.z, wb.w};
            #pragma unroll
            for (int j = 0; j < 4; j++) {
                F2U wda; wda.f = make_float2(was[j], was[j]);
                F2U wdb; wdb.f = make_float2(wbs[j], wbs[j]);
                ffma2(acc00, wda, za[j]);
                ffma2(acc01, wda, zb[j]);
                ffma2(acc10, wdb, za[j]);
                ffma2(acc11, wdb, zb[j]);
            }
        }
        __syncthreads();
    }

    // write partials: scratch[kb][n][t], pair covers t = 2*tp .. 2*tp+1
    float2* sc = (float2*)g_scratch;
    size_t base = (size_t)kb * NOUT;
    sc[((base + row0 + ra) * TT + 2 * tp0) >> 1]       = acc00.f;
    sc[((base + row0 + ra) * TT + 2 * (tp0 + 1)) >> 1] = acc01.f;
    sc[((base + row0 + rb) * TT + 2 * tp0) >> 1]       = acc10.f;
    sc[((base + row0 + rb) * TT + 2 * (tp0 + 1)) >> 1] = acc11.f;
}

// ---------- kernel 4: epilogue — sum partials + bias + tanh ----------
__global__ void epilogue_kernel(const float* __restrict__ bias,
                                float* __restrict__ out) {
    int n = blockIdx.x * blockDim.x + threadIdx.x;
    if (n >= NOUT) return;
    float s[TT];
    #pragma unroll
    for (int t = 0; t < TT; t++) s[t] = 0.f;
    #pragma unroll
    for (int kb = 0; kb < KSPLIT; kb++) {
        const float4* p = (const float4*)&g_scratch[((size_t)kb * NOUT + n) * TT];
        #pragma unroll
        for (int q = 0; q < 4; q++) {
            float4 v = p[q];
            s[q*4+0] += v.x; s[q*4+1] += v.y; s[q*4+2] += v.z; s[q*4+3] += v.w;
        }
    }
    float b = bias[n];
    #pragma unroll
    for (int t = 0; t < TT; t++)
        out[(size_t)t * NOUT + n] = tanhf(s[t] + b);
}

extern "C" void kernel_launch(void* const* d_in, const int* in_sizes, int n_in,
                              void* d_out, int out_size) {
    const float* relations = (const float*)d_in[0];
    const float* factors   = (const float*)d_in[1];
    const float* W_dyn     = (const float*)d_in[2];
    const float* b_dyn     = (const float*)d_in[3];
    const int*   t_idx     = (const int*)d_in[4];
    float* out = (float*)d_out;

    int smem = (2 * WBUF + 2 * ZBUF) * (int)sizeof(float);   // 78080
    cudaFuncSetAttribute(mlp_kernel, cudaFuncAttributeMaxDynamicSharedMemorySize, smem);

    gather_kernel<<<625, 256>>>(factors, t_idx);
    gemm1_kernel<<<125, 128>>>(relations);
    pack_kernel<<<(8 * KDIM + 255) / 256, 256>>>();
    dim3 grid(63, KSPLIT);
    mlp_kernel<<<grid, 256, smem>>>(W_dyn);
    epilogue_kernel<<<(NOUT + 255) / 256, 256>>>(b_dyn, out);
}

// round 6
// speedup vs baseline: 1.5973x; 1.0039x over previous
#include <cuda_runtime.h>
#include <math.h>
#include <stdint.h>

#define NX    2000
#define NZ    4
#define TT    16
#define KDIM  24000   // 3*2000*4
#define NOUT  8000    // nz*nx
#define NCOL  64      // TT*NZ

#define KSPLIT 9
#define NTILES 375    // 24000/64
#define TPK    42     // ceil(375/9)
#define KT     64

__device__ float  g_zctx[TT * KDIM];          // (16, 24000)
__device__ float  g_zg[NX * NCOL];            // (2000, 64)
__device__ float2 g_zpair[8 * KDIM];          // [tp][k] = (z[2tp][k], z[2tp+1][k])
__device__ float  g_scratch[KSPLIT * NOUT * TT];  // [kb][n][t]

union F2U { float2 f; unsigned long long u; };
__device__ __forceinline__ void ffma2(F2U& d, const F2U a, const F2U b) {
    asm("fma.rn.f32x2 %0, %1, %2, %0;" : "+l"(d.u) : "l"(a.u), "l"(b.u));
}
__device__ __forceinline__ uint32_t s2u(const void* p) {
    uint32_t a;
    asm("{ .reg .u64 t; cvta.to.shared.u64 t, %1; cvt.u32.u64 %0, t; }" : "=r"(a) : "l"(p));
    return a;
}
#define CP16(dst, src) asm volatile("cp.async.cg.shared.global [%0], [%1], 16;" :: "r"(dst), "l"(src))
#define CP_COMMIT()    asm volatile("cp.async.commit_group;")
#define CP_WAIT(N)     asm volatile("cp.async.wait_group %0;" :: "n"(N))

// ---------- kernel 1: gather ----------
__global__ void gather_kernel(const float* __restrict__ factors,
                              const int*   __restrict__ t_idx) {
    int gid = blockIdx.x * blockDim.x + threadIdx.x;
    if (gid < NX * NCOL) {
        int y = gid >> 6, n = gid & 63;
        int t = n >> 2, zi = n & 3;
        g_zg[gid] = factors[(long)t_idx[t] * NOUT + y * NZ + zi];
    } else {
        int i = gid - NX * NCOL;
        if (i < TT * NOUT / 4) {
            int t = i / (NOUT / 4);
            int j = i - t * (NOUT / 4);
            float4 v = ((const float4*)factors)[(long)t_idx[t] * (NOUT / 4) + j];
            ((float4*)g_zctx)[(long)t * (KDIM / 4) + j] = v;
        }
    }
}

// ---------- kernel 2: relation GEMM (4000x2000)@(2000x64) ----------
#define KT1 100
__global__ __launch_bounds__(128) void gemm1_kernel(const float* __restrict__ rel) {
    __shared__ float rel_sT[KT1][36];
    __shared__ float zg_s[KT1][64];
    int tid = threadIdx.x;
    int mg = tid >> 4, ng = tid & 15;
    int mbase = blockIdx.x * 32;

    F2U acc[2][4];
    #pragma unroll
    for (int a = 0; a < 2; a++)
        #pragma unroll
        for (int b = 0; b < 4; b++) acc[a][b].f = make_float2(0.f, 0.f);

    for (int kt = 0; kt < NX; kt += KT1) {
        for (int i = tid; i < 32 * (KT1 / 4); i += 128) {
            int m = i / (KT1 / 4), q = i - m * (KT1 / 4);
            float4 v = *(const float4*)&rel[(long)(mbase + m) * NX + kt + q * 4];
            rel_sT[q*4+0][m] = v.x; rel_sT[q*4+1][m] = v.y;
            rel_sT[q*4+2][m] = v.z; rel_sT[q*4+3][m] = v.w;
        }
        for (int i = tid; i < KT1 * 64 / 4; i += 128)
            ((float4*)zg_s)[i] = ((const float4*)(g_zg + kt * 64))[i];
        __syncthreads();

        #pragma unroll 4
        for (int k = 0; k < KT1; k++) {
            float4 a4 = *(float4*)&rel_sT[k][mg * 4];
            float4 b4 = *(float4*)&zg_s[k][ng * 4];
            F2U a2[2];
            a2[0].f = make_float2(a4.x, a4.y);
            a2[1].f = make_float2(a4.z, a4.w);
            float bb[4] = {b4.x, b4.y, b4.z, b4.w};
            #pragma unroll
            for (int j = 0; j < 4; j++) {
                F2U b2; b2.f = make_float2(bb[j], bb[j]);
                ffma2(acc[0][j], a2[0], b2);
                ffma2(acc[1][j], a2[1], b2);
            }
        }
        __syncthreads();
    }
    #pragma unroll
    for (int mp = 0; mp < 2; mp++)
        #pragma unroll
        for (int j = 0; j < 4; j++) {
            int m0 = mbase + mg * 4 + mp * 2;
            float2 v = acc[mp][j].f;
            g_zctx[(long)ng * KDIM + 1 * NOUT + (m0 >> 1) * NZ + j] = v.x;
            g_zctx[(long)ng * KDIM + 2 * NOUT + (m0 >> 1) * NZ + j] = v.y;
        }
}

// ---------- kernel 2.5: pack z into t-pairs ----------
__global__ void pack_kernel() {
    int gid = blockIdx.x * blockDim.x + threadIdx.x;
    if (gid < 8 * KDIM) {
        int tp = gid / KDIM, k = gid - tp * KDIM;
        g_zpair[gid] = make_float2(g_zctx[(2*tp) * KDIM + k],
                                   g_zctx[(2*tp + 1) * KDIM + k]);
    }
}

// ---------- kernel 3: MLP partial GEMM, double-buffered cp.async ----------
// smem: W [2][128][68] floats (69632 B) + Z [2][8][132] floats (8448 B) = 78080 B
#define WSTRIDE 68
#define ZSTRIDE 132           // floats per tp row (66 float2)
#define WBUF    (128 * WSTRIDE)
#define ZBASE   (2 * WBUF)
#define ZBUF    (8 * ZSTRIDE)

__global__ __launch_bounds__(256) void mlp_kernel(const float* __restrict__ W) {
    extern __shared__ float sm[];
    int tid  = threadIdx.x;
    int lane = tid & 31, warp = tid >> 5;
    int rowblk = blockIdx.x, kb = blockIdx.y;

    int row0 = rowblk * 128;
    if (row0 > NOUT - 128) row0 = NOUT - 128;     // benign duplicate rows
    int t0 = kb * TPK;
    int t1 = t0 + TPK; if (t1 > NTILES) t1 = NTILES;
    int nt = t1 - t0;

    // thread tile: rows (ra, ra+64) x t-pairs (tp0, tp0+1)
    int rg  = lane >> 2;            // 0..7
    int tpg = lane & 3;             // 0..3
    int ra  = warp * 8 + rg;        // 0..63
    int rb  = ra + 64;
    int tp0 = tpg * 2;

    F2U acc00, acc01, acc10, acc11;
    acc00.f = acc01.f = acc10.f = acc11.f = make_float2(0.f, 0.f);

    auto load_tile = [&](int tile, int buf) {
        int k0 = (t0 + tile) * KT;
        // W: 128 rows x 64 floats = 2048 CP16s of 4 floats
        #pragma unroll
        for (int j = 0; j < 8; j++) {
            int c = j * 256 + tid;
            int row = c >> 4, q = c & 15;
            uint32_t dst = s2u(&sm[buf * WBUF + row * WSTRIDE + q * 4]);
            const float* src = &W[(size_t)(row0 + row) * KDIM + k0 + q * 4];
            CP16(dst, src);
        }
        // Z: 8 tp-rows x 64 float2 = 256 CP16s
        {
            int tp = tid >> 5, ch = tid & 31;
            uint32_t dst = s2u(&sm[ZBASE + buf * ZBUF + tp * ZSTRIDE + ch * 4]);
            const float2* src = &g_zpair[tp * KDIM + k0 + ch * 2];
            CP16(dst, src);
        }
        CP_COMMIT();
    };

    load_tile(0, 0);
    for (int i = 0; i < nt; i++) {
        int buf = i & 1;
        if (i + 1 < nt) { load_tile(i + 1, buf ^ 1); CP_WAIT(1); }
        else           { CP_WAIT(0); }
        __syncthreads();

        const float* Wt = &sm[buf * WBUF];
        const float* Zt = &sm[ZBASE + buf * ZBUF];
        #pragma unroll 4
        for (int kk = 0; kk < KT; kk += 4) {
            float4 wa = *(const float4*)&Wt[ra * WSTRIDE + kk];
            float4 wb = *(const float4*)&Wt[rb * WSTRIDE + kk];
            float4 z0a = *(const float4*)&Zt[tp0 * ZSTRIDE + kk * 2];
            float4 z0b = *(const float4*)&Zt[tp0 * ZSTRIDE + kk * 2 + 4];
            float4 z1a = *(const float4*)&Zt[(tp0 + 1) * ZSTRIDE + kk * 2];
            float4 z1b = *(const float4*)&Zt[(tp0 + 1) * ZSTRIDE + kk * 2 + 4];
            F2U za[4], zb[4];
            za[0].f = make_float2(z0a.x, z0a.y); za[1].f = make_float2(z0a.z, z0a.w);
            za[2].f = make_float2(z0b.x, z0b.y); za[3].f = make_float2(z0b.z, z0b.w);
            zb[0].f = make_float2(z1a.x, z1a.y); zb[1].f = make_float2(z1a.z, z1a.w);
            zb[2].f = make_float2(z1b.x, z1b.y); zb[3].f = make_float2(z1b.z, z1b.w);
            float was[4] = {wa.x, wa.y, wa.z, wa.w};
            float wbs[4] = {wb.x, wb.y, wb.z, wb.w};
            #pragma unroll
            for (int j = 0; j < 4; j++) {
                F2U wda; wda.f = make_float2(was[j], was[j]);
                F2U wdb; wdb.f = make_float2(wbs[j], wbs[j]);
                ffma2(acc00, wda, za[j]);
                ffma2(acc01, wda, zb[j]);
                ffma2(acc10, wdb, za[j]);
                ffma2(acc11, wdb, zb[j]);
            }
        }
        __syncthreads();
    }

    // write partials: scratch[kb][n][t], pair covers t = 2*tp .. 2*tp+1
    float2* sc = (float2*)g_scratch;
    size_t base = (size_t)kb * NOUT;
    sc[((base + row0 + ra) * TT + 2 * tp0) >> 1]       = acc00.f;
    sc[((base + row0 + ra) * TT + 2 * (tp0 + 1)) >> 1] = acc01.f;
    sc[((base + row0 + rb) * TT + 2 * tp0) >> 1]       = acc10.f;
    sc[((base + row0 + rb) * TT + 2 * (tp0 + 1)) >> 1] = acc11.f;
}

// ---------- kernel 4: epilogue — sum partials + bias + tanh ----------
__global__ void epilogue_kernel(const float* __restrict__ bias,
                                float* __restrict__ out) {
    int n = blockIdx.x * blockDim.x + threadIdx.x;
    if (n >= NOUT) return;
    float s[TT];
    #pragma unroll
    for (int t = 0; t < TT; t++) s[t] = 0.f;
    #pragma unroll
    for (int kb = 0; kb < KSPLIT; kb++) {
        const float4* p = (const float4*)&g_scratch[((size_t)kb * NOUT + n) * TT];
        #pragma unroll
        for (int q = 0; q < 4; q++) {
            float4 v = p[q];
            s[q*4+0] += v.x; s[q*4+1] += v.y; s[q*4+2] += v.z; s[q*4+3] += v.w;
        }
    }
    float b = bias[n];
    #pragma unroll
    for (int t = 0; t < TT; t++)
        out[(size_t)t * NOUT + n] = tanhf(s[t] + b);
}

extern "C" void kernel_launch(void* const* d_in, const int* in_sizes, int n_in,
                              void* d_out, int out_size) {
    const float* relations = (const float*)d_in[0];
    const float* factors   = (const float*)d_in[1];
    const float* W_dyn     = (const float*)d_in[2];
    const float* b_dyn     = (const float*)d_in[3];
    const int*   t_idx     = (const int*)d_in[4];
    float* out = (float*)d_out;

    int smem = (2 * WBUF + 2 * ZBUF) * (int)sizeof(float);   // 78080
    cudaFuncSetAttribute(mlp_kernel, cudaFuncAttributeMaxDynamicSharedMemorySize, smem);

    gather_kernel<<<625, 256>>>(factors, t_idx);
    gemm1_kernel<<<125, 128>>>(relations);
    pack_kernel<<<(8 * KDIM + 255) / 256, 256>>>();
    dim3 grid(63, KSPLIT);
    mlp_kernel<<<grid, 256, smem>>>(W_dyn);
    epilogue_kernel<<<(NOUT + 255) / 256, 256>>>(b_dyn, out);
}

// round 7
// speedup vs baseline: 1.6288x; 1.0197x over previous
#include <cuda_runtime.h>
#include <math.h>
#include <stdint.h>

#define NX    2000
#define NZ    4
#define TT    16
#define KDIM  24000   // 3*2000*4
#define NOUT  8000    // nz*nx
#define NCOL  64      // TT*NZ

#define KSPLIT 11
#define KT     32
#define NTILES (KDIM / KT)        // 750
#define TPK    69                 // ceil(750/11)

__device__ float  g_zctx[TT * KDIM];              // (16, 24000)
__device__ float  g_zg[NX * NCOL];                // (2000, 64)
__device__ float2 g_zpair[8 * KDIM];              // [tp][k] = (z[2tp][k], z[2tp+1][k])
__device__ float  g_scratch[KSPLIT * NOUT * TT];  // [kb][n][t]

union F2U { float2 f; unsigned long long u; };
__device__ __forceinline__ void ffma2(F2U& d, const F2U a, const F2U b) {
    asm("fma.rn.f32x2 %0, %1, %2, %0;" : "+l"(d.u) : "l"(a.u), "l"(b.u));
}
__device__ __forceinline__ uint32_t s2u(const void* p) {
    uint32_t a;
    asm("{ .reg .u64 t; cvta.to.shared.u64 t, %1; cvt.u32.u64 %0, t; }" : "=r"(a) : "l"(p));
    return a;
}
#define CP16(dst, src) asm volatile("cp.async.cg.shared.global [%0], [%1], 16;" :: "r"(dst), "l"(src))
#define CP_COMMIT()    asm volatile("cp.async.commit_group;")
#define CP_WAIT(N)     asm volatile("cp.async.wait_group %0;" :: "n"(N))

// ---------- kernel 1: gather ----------
__global__ void gather_kernel(const float* __restrict__ factors,
                              const int*   __restrict__ t_idx) {
    int gid = blockIdx.x * blockDim.x + threadIdx.x;
    if (gid < NX * NCOL) {
        int y = gid >> 6, n = gid & 63;
        int t = n >> 2, zi = n & 3;
        g_zg[gid] = factors[(long)t_idx[t] * NOUT + y * NZ + zi];
    } else {
        int i = gid - NX * NCOL;
        if (i < TT * NOUT / 4) {
            int t = i / (NOUT / 4);
            int j = i - t * (NOUT / 4);
            float4 v = ((const float4*)factors)[(long)t_idx[t] * (NOUT / 4) + j];
            ((float4*)g_zctx)[(long)t * (KDIM / 4) + j] = v;
        }
    }
}

// ---------- kernel 2: relation GEMM (4000x2000)@(2000x64) ----------
#define KT1 100
__global__ __launch_bounds__(128) void gemm1_kernel(const float* __restrict__ rel) {
    __shared__ float rel_sT[KT1][36];
    __shared__ float zg_s[KT1][64];
    int tid = threadIdx.x;
    int mg = tid >> 4, ng = tid & 15;
    int mbase = blockIdx.x * 32;

    F2U acc[2][4];
    #pragma unroll
    for (int a = 0; a < 2; a++)
        #pragma unroll
        for (int b = 0; b < 4; b++) acc[a][b].f = make_float2(0.f, 0.f);

    for (int kt = 0; kt < NX; kt += KT1) {
        // conflict-free transpose store: lane = m (32 banks), q = k-chunk
        for (int i = tid; i < 32 * (KT1 / 4); i += 128) {
            int m = i & 31, q = i >> 5;
            float4 v = *(const float4*)&rel[(long)(mbase + m) * NX + kt + q * 4];
            rel_sT[q*4+0][m] = v.x; rel_sT[q*4+1][m] = v.y;
            rel_sT[q*4+2][m] = v.z; rel_sT[q*4+3][m] = v.w;
        }
        for (int i = tid; i < KT1 * 64 / 4; i += 128)
            ((float4*)zg_s)[i] = ((const float4*)(g_zg + kt * 64))[i];
        __syncthreads();

        #pragma unroll 4
        for (int k = 0; k < KT1; k++) {
            float4 a4 = *(float4*)&rel_sT[k][mg * 4];
            float4 b4 = *(float4*)&zg_s[k][ng * 4];
            F2U a2[2];
            a2[0].f = make_float2(a4.x, a4.y);
            a2[1].f = make_float2(a4.z, a4.w);
            float bb[4] = {b4.x, b4.y, b4.z, b4.w};
            #pragma unroll
            for (int j = 0; j < 4; j++) {
                F2U b2; b2.f = make_float2(bb[j], bb[j]);
                ffma2(acc[0][j], a2[0], b2);
                ffma2(acc[1][j], a2[1], b2);
            }
        }
        __syncthreads();
    }
    #pragma unroll
    for (int mp = 0; mp < 2; mp++)
        #pragma unroll
        for (int j = 0; j < 4; j++) {
            int m0 = mbase + mg * 4 + mp * 2;
            float2 v = acc[mp][j].f;
            g_zctx[(long)ng * KDIM + 1 * NOUT + (m0 >> 1) * NZ + j] = v.x;
            g_zctx[(long)ng * KDIM + 2 * NOUT + (m0 >> 1) * NZ + j] = v.y;
        }
}

// ---------- kernel 2.5: pack z into t-pairs ----------
__global__ void pack_kernel() {
    int gid = blockIdx.x * blockDim.x + threadIdx.x;
    if (gid < 8 * KDIM) {
        int tp = gid / KDIM, k = gid - tp * KDIM;
        g_zpair[gid] = make_float2(g_zctx[(2*tp) * KDIM + k],
                                   g_zctx[(2*tp + 1) * KDIM + k]);
    }
}

// ---------- kernel 3: MLP partial GEMM, double-buffered cp.async ----------
// smem: W [2][128][36] (36864 B) + Z [2][8][68] (4352 B) = 41216 B -> 5 blocks/SM
#define WSTRIDE 36
#define ZSTRIDE 68            // floats per tp row (32 float2 + pad), %4==0 for LDS.128
#define WBUF    (128 * WSTRIDE)
#define ZBASE   (2 * WBUF)
#define ZBUF    (8 * ZSTRIDE)

__global__ __launch_bounds__(256, 5) void mlp_kernel(const float* __restrict__ W) {
    extern __shared__ float sm[];
    int tid  = threadIdx.x;
    int lane = tid & 31, warp = tid >> 5;
    int rowblk = blockIdx.x, kb = blockIdx.y;

    int row0 = rowblk * 128;
    if (row0 > NOUT - 128) row0 = NOUT - 128;     // benign duplicate rows
    int t0 = kb * TPK;
    int t1 = t0 + TPK; if (t1 > NTILES) t1 = NTILES;
    int nt = t1 - t0;

    // thread tile: rows (ra, ra+64) x t-pairs (tp0, tp0+1)
    int rg  = lane >> 2;            // 0..7
    int tpg = lane & 3;             // 0..3
    int ra  = warp * 8 + rg;        // 0..63
    int rb  = ra + 64;
    int tp0 = tpg * 2;

    F2U acc00, acc01, acc10, acc11;
    acc00.f = acc01.f = acc10.f = acc11.f = make_float2(0.f, 0.f);

    auto load_tile = [&](int tile, int buf) {
        int k0 = (t0 + tile) * KT;
        // W: 128 rows x 32 floats = 1024 CP16s
        #pragma unroll
        for (int j = 0; j < 4; j++) {
            int c = j * 256 + tid;
            int row = c >> 3, q = c & 7;
            uint32_t dst = s2u(&sm[buf * WBUF + row * WSTRIDE + q * 4]);
            const float* src = &W[(size_t)(row0 + row) * KDIM + k0 + q * 4];
            CP16(dst, src);
        }
        // Z: 8 tp-rows x 32 float2 = 128 CP16s
        if (tid < 128) {
            int tp = tid >> 4, ch = tid & 15;
            uint32_t dst = s2u(&sm[ZBASE + buf * ZBUF + tp * ZSTRIDE + ch * 4]);
            const float2* src = &g_zpair[tp * KDIM + k0 + ch * 2];
            CP16(dst, src);
        }
        CP_COMMIT();
    };

    load_tile(0, 0);
    for (int i = 0; i < nt; i++) {
        int buf = i & 1;
        if (i + 1 < nt) { load_tile(i + 1, buf ^ 1); CP_WAIT(1); }
        else           { CP_WAIT(0); }
        __syncthreads();

        const float* Wt = &sm[buf * WBUF];
        const float* Zt = &sm[ZBASE + buf * ZBUF];
        #pragma unroll 4
        for (int kk = 0; kk < KT; kk += 4) {
            float4 wa = *(const float4*)&Wt[ra * WSTRIDE + kk];
            float4 wb = *(const float4*)&Wt[rb * WSTRIDE + kk];
            float4 z0a = *(const float4*)&Zt[tp0 * ZSTRIDE + kk * 2];
            float4 z0b = *(const float4*)&Zt[tp0 * ZSTRIDE + kk * 2 + 4];
            float4 z1a = *(const float4*)&Zt[(tp0 + 1) * ZSTRIDE + kk * 2];
            float4 z1b = *(const float4*)&Zt[(tp0 + 1) * ZSTRIDE + kk * 2 + 4];
            F2U za[4], zb[4];
            za[0].f = make_float2(z0a.x, z0a.y); za[1].f = make_float2(z0a.z, z0a.w);
            za[2].f = make_float2(z0b.x, z0b.y); za[3].f = make_float2(z0b.z, z0b.w);
            zb[0].f = make_float2(z1a.x, z1a.y); zb[1].f = make_float2(z1a.z, z1a.w);
            zb[2].f = make_float2(z1b.x, z1b.y); zb[3].f = make_float2(z1b.z, z1b.w);
            float was[4] = {wa.x, wa.y, wa.z, wa.w};
            float wbs[4] = {wb.x, wb.y, wb.z, wb.w};
            #pragma unroll
            for (int j = 0; j < 4; j++) {
                F2U wda; wda.f = make_float2(was[j], was[j]);
                F2U wdb; wdb.f = make_float2(wbs[j], wbs[j]);
                ffma2(acc00, wda, za[j]);
                ffma2(acc01, wda, zb[j]);
                ffma2(acc10, wdb, za[j]);
                ffma2(acc11, wdb, zb[j]);
            }
        }
        __syncthreads();
    }

    float2* sc = (float2*)g_scratch;
    size_t base = (size_t)kb * NOUT;
    sc[((base + row0 + ra) * TT + 2 * tp0) >> 1]       = acc00.f;
    sc[((base + row0 + ra) * TT + 2 * (tp0 + 1)) >> 1] = acc01.f;
    sc[((base + row0 + rb) * TT + 2 * tp0) >> 1]       = acc10.f;
    sc[((base + row0 + rb) * TT + 2 * (tp0 + 1)) >> 1] = acc11.f;
}

// ---------- kernel 4: epilogue — sum partials + bias + tanh ----------
// thread = (n, t-quad): 32000 threads, coalesced float4 scratch reads
__global__ void epilogue_kernel(const float* __restrict__ bias,
                                float* __restrict__ out) {
    int idx = blockIdx.x * blockDim.x + threadIdx.x;
    if (idx >= NOUT * 4) return;
    int n = idx >> 2, tq = idx & 3;
    float4 s = make_float4(0.f, 0.f, 0.f, 0.f);
    #pragma unroll
    for (int kb = 0; kb < KSPLIT; kb++) {
        float4 v = *(const float4*)&g_scratch[((size_t)kb * NOUT + n) * TT + tq * 4];
        s.x += v.x; s.y += v.y; s.z += v.z; s.w += v.w;
    }
    float b = bias[n];
    out[(size_t)(tq*4+0) * NOUT + n] = tanhf(s.x + b);
    out[(size_t)(tq*4+1) * NOUT + n] = tanhf(s.y + b);
    out[(size_t)(tq*4+2) * NOUT + n] = tanhf(s.z + b);
    out[(size_t)(tq*4+3) * NOUT + n] = tanhf(s.w + b);
}

extern "C" void kernel_launch(void* const* d_in, const int* in_sizes, int n_in,
                              void* d_out, int out_size) {
    const float* relations = (const float*)d_in[0];
    const float* factors   = (const float*)d_in[1];
    const float* W_dyn     = (const float*)d_in[2];
    const float* b_dyn     = (const float*)d_in[3];
    const int*   t_idx     = (const int*)d_in[4];
    float* out = (float*)d_out;

    int smem = (2 * WBUF + 2 * ZBUF) * (int)sizeof(float);   // 41216
    cudaFuncSetAttribute(mlp_kernel, cudaFuncAttributeMaxDynamicSharedMemorySize, smem);

    gather_kernel<<<625, 256>>>(factors, t_idx);
    gemm1_kernel<<<125, 128>>>(relations);
    pack_kernel<<<(8 * KDIM + 255) / 256, 256>>>();
    dim3 grid(63, KSPLIT);
    mlp_kernel<<<grid, 256, smem>>>(W_dyn);
    epilogue_kernel<<<(NOUT * 4 + 255) / 256, 256>>>(b_dyn, out);
}

// round 8
// speedup vs baseline: 1.7746x; 1.0895x over previous
#include <cuda_runtime.h>
#include <math.h>
#include <stdint.h>

#define NX    2000
#define NZ    4
#define TT    16
#define KDIM  24000   // 3*2000*4
#define NOUT  8000    // nz*nx
#define NCOL  64      // TT*NZ

#define KSPLIT 9
#define KT     32
#define NTILES (KDIM / KT)        // 750
#define TPK    84                 // ceil(750/9)

__device__ float  g_zg[NX * NCOL];                // (2000, 64)
__device__ float2 g_zpair[8 * KDIM];              // [tp][k] = (z[2tp][k], z[2tp+1][k])
__device__ float  g_scratch[KSPLIT * NOUT * TT];  // [kb][n][t]

union F2U { float2 f; unsigned long long u; };
__device__ __forceinline__ void ffma2(F2U& d, const F2U a, const F2U b) {
    asm("fma.rn.f32x2 %0, %1, %2, %0;" : "+l"(d.u) : "l"(a.u), "l"(b.u));
}
__device__ __forceinline__ uint32_t s2u(const void* p) {
    uint32_t a;
    asm("{ .reg .u64 t; cvta.to.shared.u64 t, %1; cvt.u32.u64 %0, t; }" : "=r"(a) : "l"(p));
    return a;
}
__device__ __forceinline__ void bulk_g2s(uint32_t dst, const void* src, int bytes, uint32_t mbar) {
    asm volatile("cp.async.bulk.shared::cta.global.mbarrier::complete_tx::bytes [%0], [%1], %2, [%3];"
                 :: "r"(dst), "l"(src), "r"(bytes), "r"(mbar) : "memory");
}
__device__ __forceinline__ void mbar_init(uint32_t mbar, int cnt) {
    asm volatile("mbarrier.init.shared.b64 [%0], %1;" :: "r"(mbar), "r"(cnt) : "memory");
}
__device__ __forceinline__ void mbar_expect(uint32_t mbar, int bytes) {
    asm volatile("mbarrier.arrive.expect_tx.shared.b64 _, [%0], %1;" :: "r"(mbar), "r"(bytes) : "memory");
}
__device__ __forceinline__ void mbar_wait(uint32_t mbar, int phase) {
    asm volatile("{\n\t.reg .pred P;\n\t"
                 "WL_%=:\n\t"
                 "mbarrier.try_wait.parity.acquire.cta.shared::cta.b64 P, [%0], %1, 0x989680;\n\t"
                 "@P bra.uni WD_%=;\n\t"
                 "bra.uni WL_%=;\n\t"
                 "WD_%=:\n\t}"
                 :: "r"(mbar), "r"(phase) : "memory");
}

// ---------- kernel 1: gather g_zg ----------
__global__ void gather_kernel(const float* __restrict__ factors,
                              const int*   __restrict__ t_idx) {
    int gid = blockIdx.x * blockDim.x + threadIdx.x;
    if (gid < NX * NCOL) {
        int y = gid >> 6, n = gid & 63;
        int t = n >> 2, zi = n & 3;
        g_zg[gid] = factors[(long)t_idx[t] * NOUT + y * NZ + zi];
    }
}

// ---------- kernel 2: relation GEMM (4000x2000)@(2000x64), scatter into zpair ----------
#define KT1 100
__global__ __launch_bounds__(256) void gemm1_kernel(const float* __restrict__ rel) {
    __shared__ float rel_sT[KT1][36];
    __shared__ float zg_s[KT1][64];
    int tid = threadIdx.x;
    int mg = tid >> 5, ng = tid & 31;      // 8 m-groups x 32 n-groups
    int mbase = blockIdx.x * 32;

    F2U acc[2][2];
    acc[0][0].f = acc[0][1].f = acc[1][0].f = acc[1][1].f = make_float2(0.f, 0.f);

    for (int kt = 0; kt < NX; kt += KT1) {
        for (int i = tid; i < 800; i += 256) {           // 32 m x 25 q
            int m = i & 31, q = i >> 5;
            float4 v = *(const float4*)&rel[(long)(mbase + m) * NX + kt + q * 4];
            rel_sT[q*4+0][m] = v.x; rel_sT[q*4+1][m] = v.y;
            rel_sT[q*4+2][m] = v.z; rel_sT[q*4+3][m] = v.w;
        }
        for (int i = tid; i < KT1 * 64 / 4; i += 256)
            ((float4*)zg_s)[i] = ((const float4*)(g_zg + kt * 64))[i];
        __syncthreads();

        #pragma unroll 4
        for (int k = 0; k < KT1; k++) {
            float4 a4 = *(float4*)&rel_sT[k][mg * 4];
            float2 b2 = *(float2*)&zg_s[k][ng * 2];
            F2U a2[2];
            a2[0].f = make_float2(a4.x, a4.y);
            a2[1].f = make_float2(a4.z, a4.w);
            F2U b0; b0.f = make_float2(b2.x, b2.x);
            F2U b1; b1.f = make_float2(b2.y, b2.y);
            ffma2(acc[0][0], a2[0], b0);
            ffma2(acc[1][0], a2[1], b0);
            ffma2(acc[0][1], a2[0], b1);
            ffma2(acc[1][1], a2[1], b1);
        }
        __syncthreads();
    }
    // scatter: m0 even -> r=1 (.x), m0+1 odd -> r=2 (.y); col n = ng*2+j
    float* zp = (float*)g_zpair;
    #pragma unroll
    for (int mp = 0; mp < 2; mp++)
        #pragma unroll
        for (int j = 0; j < 2; j++) {
            int m0 = mbase + mg * 4 + mp * 2;
            int x  = m0 >> 1;
            int n  = ng * 2 + j;
            int t  = n >> 2, z = n & 3;
            int tp = t >> 1, half = t & 1;
            float2 v = acc[mp][j].f;
            zp[((size_t)tp * KDIM +  8000 + x * 4 + z) * 2 + half] = v.x;
            zp[((size_t)tp * KDIM + 16000 + x * 4 + z) * 2 + half] = v.y;
        }
}

// ---------- kernel 2.5: pack identity region (k < 8000) from factors ----------
__global__ void pack_kernel(const float* __restrict__ factors,
                            const int*   __restrict__ t_idx) {
    int gid = blockIdx.x * blockDim.x + threadIdx.x;
    if (gid >= 8 * NOUT) return;
    int tp = gid / NOUT, k = gid - tp * NOUT;
    int i0 = t_idx[2 * tp], i1 = t_idx[2 * tp + 1];
    g_zpair[(size_t)tp * KDIM + k] =
        make_float2(factors[(size_t)i0 * NOUT + k], factors[(size_t)i1 * NOUT + k]);
}

// ---------- kernel 3: MLP partial GEMM — bulk-copy double-buffered ----------
// block: 128 threads, 256 W-rows x 16 t. thread = 4 rows x 4 t-pairs.
// smem: W [2][256][36] (73728 B) + Z [2][8][68] (4352 B) + mbar -> 78112 B, 2 blocks/SM
#define WSTRIDE 36
#define ZSTRIDE 68
#define WBUFF   (256 * WSTRIDE)          // floats
#define ZBASE   (2 * WBUFF)
#define ZBUFF   (8 * ZSTRIDE)
#define MBAR_OFF ((ZBASE + 2 * ZBUFF) * 4)
#define SMEM_BYTES (MBAR_OFF + 32)
#define TILE_BYTES (256 * 128 + 8 * 256) // 34816

__global__ __launch_bounds__(128, 2) void mlp_kernel(const float* __restrict__ W) {
    extern __shared__ float sm[];
    uint32_t sb = s2u(sm);
    int tid = threadIdx.x, lane = tid & 31, warp = tid >> 5;
    int rowblk = blockIdx.x, kb = blockIdx.y;

    int row0 = rowblk * 256;
    if (row0 > NOUT - 256) row0 = NOUT - 256;     // benign duplicate rows
    int t0 = kb * TPK;
    int t1 = t0 + TPK; if (t1 > NTILES) t1 = NTILES;
    int nt = t1 - t0;

    int rg  = lane >> 1;            // 0..15
    int tpg = lane & 1;             // 0..1
    int tp0 = tpg * 4;              // 4 t-pairs per thread
    int r_loc = warp * 64 + rg;     // rows r_loc + 16*i, i=0..3

    uint32_t mb = sb + MBAR_OFF;
    if (tid == 0) { mbar_init(mb, 1); mbar_init(mb + 8, 1); }
    __syncthreads();
    int ph0 = 0, ph1 = 0;

    F2U acc[4][4];
    #pragma unroll
    for (int i = 0; i < 4; i++)
        #pragma unroll
        for (int j = 0; j < 4; j++) acc[i][j].f = make_float2(0.f, 0.f);

    const float2* zp = g_zpair;

    auto bulk_load = [&](int tile, int buf) {
        int k0 = (t0 + tile) * KT;
        // W: 256 rows, two per thread (tid, tid+128)
        uint32_t mbar = mb + buf * 8;
        bulk_g2s(sb + (buf * WBUFF + tid * WSTRIDE) * 4,
                 W + (size_t)(row0 + tid) * KDIM + k0, 128, mbar);
        bulk_g2s(sb + (buf * WBUFF + (tid + 128) * WSTRIDE) * 4,
                 W + (size_t)(row0 + tid + 128) * KDIM + k0, 128, mbar);
        if (tid < 8)
            bulk_g2s(sb + (ZBASE + buf * ZBUFF + tid * ZSTRIDE) * 4,
                     (const char*)zp + ((size_t)tid * KDIM + k0) * 8, 256, mbar);
    };

    if (tid == 0) mbar_expect(mb, TILE_BYTES);
    __syncthreads();
    bulk_load(0, 0);

    for (int i = 0; i < nt; i++) {
        int buf = i & 1;
        if (i + 1 < nt) {
            if (tid == 0) mbar_expect(mb + (buf ^ 1) * 8, TILE_BYTES);
            __syncthreads();    // orders expect before bulks; buffer freed by all threads
            bulk_load(i + 1, buf ^ 1);
        }
        if (buf) { mbar_wait(mb + 8, ph1); ph1 ^= 1; }
        else     { mbar_wait(mb,     ph0); ph0 ^= 1; }

        const float* Wt = sm + buf * WBUFF;
        const float* Zt = sm + ZBASE + buf * ZBUFF;
        #pragma unroll
        for (int kk = 0; kk < KT; kk += 4) {
            float4 wv[4];
            #pragma unroll
            for (int i2 = 0; i2 < 4; i2++)
                wv[i2] = *(const float4*)&Wt[(r_loc + 16 * i2) * WSTRIDE + kk];
            F2U zf[4][4];
            #pragma unroll
            for (int j = 0; j < 4; j++) {
                float4 a = *(const float4*)&Zt[(tp0 + j) * ZSTRIDE + kk * 2];
                float4 b = *(const float4*)&Zt[(tp0 + j) * ZSTRIDE + kk * 2 + 4];
                zf[j][0].f = make_float2(a.x, a.y);
                zf[j][1].f = make_float2(a.z, a.w);
                zf[j][2].f = make_float2(b.x, b.y);
                zf[j][3].f = make_float2(b.z, b.w);
            }
            #pragma unroll
            for (int i2 = 0; i2 < 4; i2++) {
                float ws[4] = {wv[i2].x, wv[i2].y, wv[i2].z, wv[i2].w};
                #pragma unroll
                for (int q = 0; q < 4; q++) {
                    F2U w2; w2.f = make_float2(ws[q], ws[q]);
                    #pragma unroll
                    for (int j = 0; j < 4; j++)
                        ffma2(acc[i2][j], w2, zf[j][q]);
                }
            }
        }
    }

    float2* sc = (float2*)g_scratch;
    #pragma unroll
    for (int i2 = 0; i2 < 4; i2++) {
        int row = row0 + r_loc + 16 * i2;
        #pragma unroll
        for (int j = 0; j < 4; j++)
            sc[((size_t)kb * NOUT + row) * 8 + tp0 + j] = acc[i2][j].f;
    }
}

// ---------- kernel 4: epilogue — sum partials + bias + tanh ----------
__global__ void epilogue_kernel(const float* __restrict__ bias,
                                float* __restrict__ out) {
    int idx = blockIdx.x * blockDim.x + threadIdx.x;
    if (idx >= NOUT * 4) return;
    int n = idx >> 2, tq = idx & 3;
    float4 s = make_float4(0.f, 0.f, 0.f, 0.f);
    #pragma unroll
    for (int kb = 0; kb < KSPLIT; kb++) {
        float4 v = *(const float4*)&g_scratch[((size_t)kb * NOUT + n) * TT + tq * 4];
        s.x += v.x; s.y += v.y; s.z += v.z; s.w += v.w;
    }
    float b = bias[n];
    out[(size_t)(tq*4+0) * NOUT + n] = tanhf(s.x + b);
    out[(size_t)(tq*4+1) * NOUT + n] = tanhf(s.y + b);
    out[(size_t)(tq*4+2) * NOUT + n] = tanhf(s.z + b);
    out[(size_t)(tq*4+3) * NOUT + n] = tanhf(s.w + b);
}

extern "C" void kernel_launch(void* const* d_in, const int* in_sizes, int n_in,
                              void* d_out, int out_size) {
    const float* relations = (const float*)d_in[0];
    const float* factors   = (const float*)d_in[1];
    const float* W_dyn     = (const float*)d_in[2];
    const float* b_dyn     = (const float*)d_in[3];
    const int*   t_idx     = (const int*)d_in[4];
    float* out = (float*)d_out;

    cudaFuncSetAttribute(mlp_kernel, cudaFuncAttributeMaxDynamicSharedMemorySize, SMEM_BYTES);

    gather_kernel<<<(NX * NCOL + 255) / 256, 256>>>(factors, t_idx);
    gemm1_kernel<<<125, 256>>>(relations);
    pack_kernel<<<(8 * NOUT + 255) / 256, 256>>>(factors, t_idx);
    dim3 grid(32, KSPLIT);      // 32 row-blocks x 9 k-splits = 288 blocks
    mlp_kernel<<<grid, 128, SMEM_BYTES>>>(W_dyn);
    epilogue_kernel<<<(NOUT * 4 + 255) / 256, 256>>>(b_dyn, out);
}